// round 14
// baseline (speedup 1.0000x reference)
#include <cuda_runtime.h>
#include <cstdint>

constexpr int B = 2, H = 16, S = 2048, D = 64;
constexpr int NT = 512;                       // 16 warps: 8(m) x 2(n)
constexpr float SCALE = 0.125f * 1.4426950408889634f;  // (1/sqrt(64))*log2(e)

__device__ __align__(8) uint32_t g_mb[(size_t)B * S * 64];   // bit mask: 64 u32 words/row

// ---- smem map (bytes) ----
constexpr int PADK = 68;   // Q/K row pad: ldmatrix conflict-free
constexpr int PADV = 72;   // V row pad: scalar B-frags conflict-free
constexpr int PADW = 68;   // per-warp W chunk rows are 64 cols + pad
constexpr int PADR = 68;
constexpr int SM_Q  = 0;                      // [128][68]
constexpr int SM_K  = 34816;                  // [128][68]
constexpr int SM_V  = 69632;                  // [128][72]
constexpr int SM_W  = 106496;                 // 16 warps x [16][68]
constexpr int SM_SR = 176128;                 // 640 floats
constexpr int SMEM_TOT = 178688;

__device__ __forceinline__ float tf32_rna(float x) {
    uint32_t b; asm("cvt.rna.tf32.f32 %0, %1;" : "=r"(b) : "f"(x));
    return __uint_as_float(b);
}
__device__ __forceinline__ float ex2f(float x) {
    float y; asm("ex2.approx.ftz.f32 %0, %1;" : "=f"(y) : "f"(x)); return y;
}
__device__ __forceinline__ void mma8(float* c, uint32_t a0, uint32_t a1, uint32_t a2, uint32_t a3,
                                     uint32_t b0, uint32_t b1) {
    asm volatile("mma.sync.aligned.m16n8k8.row.col.f32.tf32.tf32.f32 "
                 "{%0,%1,%2,%3},{%4,%5,%6,%7},{%8,%9},{%0,%1,%2,%3};"
                 : "+f"(c[0]), "+f"(c[1]), "+f"(c[2]), "+f"(c[3])
                 : "r"(a0), "r"(a1), "r"(a2), "r"(a3), "r"(b0), "r"(b1));
}
#define LDSM4(r, a)                                                             \
    asm volatile("ldmatrix.sync.aligned.m8n8.x4.shared.b16 {%0,%1,%2,%3},[%4];" \
                 : "=r"((r)[0]), "=r"((r)[1]), "=r"((r)[2]), "=r"((r)[3]) : "r"(a))

__device__ __forceinline__ uint32_t f2u(float x) { return __float_as_uint(x); }
__device__ __forceinline__ float4 rna4(float4 x) {
    x.x = tf32_rna(x.x); x.y = tf32_rna(x.y);
    x.z = tf32_rna(x.z); x.w = tf32_rna(x.w);
    return x;
}

// ---------------- pre-kernel: mask -> bits (handles int32 or byte bool) ----------------
__global__ __launch_bounds__(256) void maskbit(const uint32_t* __restrict__ m) {
    __shared__ int swide;
    const int t = threadIdx.x, lane = t & 31, w = t >> 5;
    const size_t row = blockIdx.x;
    if (t == 0) {
        int wide = 1;
        for (int i = 0; i < 256; i++) {
            uint32_t x = m[i];
            if (x > 1u) { wide = (x == 0x3F800000u) ? 1 : 0; break; }
        }
        swide = wide;
    }
    __syncthreads();
    uint32_t* dst = g_mb + row * 64;
    if (swide) {
        const uint32_t* src = m + row * S;
        #pragma unroll
        for (int it = 0; it < 8; it++) {
            int j = (w * 8 + it) * 32 + lane;
            uint32_t bal = __ballot_sync(0xffffffffu, src[j] != 0u);
            if (lane == 0) dst[w * 8 + it] = bal;
        }
    } else {
        const unsigned char* src = reinterpret_cast<const unsigned char*>(m) + row * S;
        #pragma unroll
        for (int it = 0; it < 8; it++) {
            int j = (w * 8 + it) * 32 + lane;
            uint32_t bal = __ballot_sync(0xffffffffu, src[j] != 0);
            if (lane == 0) dst[w * 8 + it] = bal;
        }
    }
}

// ---------------- main kernel ----------------
__global__ __launch_bounds__(NT, 1)
void sdpa_mma(const float* __restrict__ q, const float* __restrict__ k,
              const float* __restrict__ v,
              float* __restrict__ out, float* __restrict__ wout)
{
    extern __shared__ char sm[];
    float* Qs = reinterpret_cast<float*>(sm + SM_Q);
    float* Ks = reinterpret_cast<float*>(sm + SM_K);
    float* Vs = reinterpret_cast<float*>(sm + SM_V);
    float* Sr = reinterpret_cast<float*>(sm + SM_SR);
    float* red = reinterpret_cast<float*>(sm);        // epilogue reuse of Q/K region

    const uint32_t SB = (uint32_t)__cvta_generic_to_shared(sm);
    const uint32_t SQ = SB + SM_Q, SKB = SB + SM_K;

    const int tid = threadIdx.x, lane = tid & 31, wid = tid >> 5;
    const int wm = wid >> 1, wn = wid & 1;             // 8(m) x 2(n)
    const int ty = lane >> 2, tx = lane & 3;

    const int bx = blockIdx.x, bh = bx >> 4, q0 = (bx & 15) * 128, b = bh >> 4;

    // per-warp private W chunk [16][PADW]
    float* Wc = reinterpret_cast<float*>(sm + SM_W) + wid * 16 * PADW;

    // ldmatrix bases
    const int lr = lane & 15;
    const int csel = (lane >> 4) * 4;
    const uint32_t qfb = SQ + (uint32_t)(((wm * 16 + lr) * PADK + csel) * 4);
    uint32_t kfb[4];
    #pragma unroll
    for (int p = 0; p < 4; p++) {
        const int krow = wn * 64 + p * 16 + ((lane >> 4) & 1) * 8 + (lane & 7);
        kfb[p] = SKB + (uint32_t)((krow * PADK + ((lane >> 3) & 1) * 4) * 4);
    }

    // ---- stage Q once (scaled, rna) ----
    {
        const float4* qg = reinterpret_cast<const float4*>(q + ((size_t)bh * S + q0) * D);
        #pragma unroll
        for (int i = 0; i < 4; i++) {
            int idx = i * NT + tid;
            int r = idx >> 4, c4 = (idx & 15) * 4;
            float4 x = qg[idx];
            x.x = tf32_rna(x.x * SCALE); x.y = tf32_rna(x.y * SCALE);
            x.z = tf32_rna(x.z * SCALE); x.w = tf32_rna(x.w * SCALE);
            *reinterpret_cast<float4*>(Qs + r * PADK + c4) = x;
        }
    }

    // ---- stage K/V tile 0 ----
    const float4* kg0 = reinterpret_cast<const float4*>(k + (size_t)bh * S * D);
    const float4* vg0 = reinterpret_cast<const float4*>(v + (size_t)bh * S * D);
    {
        #pragma unroll
        for (int i = 0; i < 4; i++) {
            int idx = i * NT + tid;
            int r = idx >> 4, c4 = (idx & 15) * 4;
            *reinterpret_cast<float4*>(Ks + r * PADK + c4) = rna4(kg0[idx]);
            *reinterpret_cast<float4*>(Vs + r * PADV + c4) = rna4(vg0[idx]);
        }
    }
    __syncthreads();

    float pacc[8][4];
    #pragma unroll
    for (int n = 0; n < 8; n++)
        #pragma unroll
        for (int i = 0; i < 4; i++) pacc[n][i] = 0.f;
    float er2[2] = {0.f, 0.f};

    // bit-mask row pointers (rows r0 = q0+wm*16+ty, r1 = +8)
    const uint32_t* mb0 = g_mb + ((size_t)(b * S + q0 + wm * 16 + ty)) * 64 + wn * 2;
    const uint32_t* mb1 = mb0 + 8 * 64;

    float4 kpre[4], vpre[4];

    for (int jt = 0; jt < 16; jt++) {
        const int j0 = jt * 128;

        // ---- prefetch next K/V tile into registers ----
        if (jt < 15) {
            const float4* kg = kg0 + (size_t)(j0 + 128) * (D / 4);
            const float4* vg = vg0 + (size_t)(j0 + 128) * (D / 4);
            #pragma unroll
            for (int i = 0; i < 4; i++) {
                kpre[i] = kg[i * NT + tid];
                vpre[i] = vg[i * NT + tid];
            }
        }

        // ---- QK^T: 16x64 block per warp ----
        float cacc[8][4];
        #pragma unroll
        for (int n = 0; n < 8; n++)
            #pragma unroll
            for (int i = 0; i < 4; i++) cacc[n][i] = 0.f;

        #pragma unroll
        for (int ks = 0; ks < 8; ks++) {
            uint32_t aa[4];
            LDSM4(aa, qfb + ks * 32);
            #pragma unroll
            for (int p = 0; p < 4; p++) {
                uint32_t bb[4];
                LDSM4(bb, kfb[p] + ks * 32);
                mma8(cacc[2 * p],     aa[0], aa[1], aa[2], aa[3], bb[0], bb[1]);
                mma8(cacc[2 * p + 1], aa[0], aa[1], aa[2], aa[3], bb[2], bb[3]);
            }
        }

        // ---- mask(bits) + exp (rna) -> Wc + cacc, accumulate row sums ----
        {
            const uint64_t w0 = *reinterpret_cast<const uint64_t*>(mb0 + jt * 4);
            const uint64_t w1 = *reinterpret_cast<const uint64_t*>(mb1 + jt * 4);
            #pragma unroll
            for (int nt = 0; nt < 8; nt++) {
                const int sh = nt * 8 + tx * 2;
                float e00 = ((w0 >> sh) & 1ull) ? 1.0f : ex2f(cacc[nt][0]);
                float e01 = ((w0 >> (sh + 1)) & 1ull) ? 1.0f : ex2f(cacc[nt][1]);
                float e10 = ((w1 >> sh) & 1ull) ? 1.0f : ex2f(cacc[nt][2]);
                float e11 = ((w1 >> (sh + 1)) & 1ull) ? 1.0f : ex2f(cacc[nt][3]);
                e00 = tf32_rna(e00); e01 = tf32_rna(e01);
                e10 = tf32_rna(e10); e11 = tf32_rna(e11);
                er2[0] += e00 + e01;
                er2[1] += e10 + e11;
                cacc[nt][0] = e00; cacc[nt][1] = e01;
                cacc[nt][2] = e10; cacc[nt][3] = e11;
                *reinterpret_cast<float2*>(Wc + ty * PADW + nt * 8 + tx * 2)       = make_float2(e00, e01);
                *reinterpret_cast<float2*>(Wc + (ty + 8) * PADW + nt * 8 + tx * 2) = make_float2(e10, e11);
            }
        }

        // ---- warp-local W chunk -> gmem (coalesced; DEFAULT policy: stay in L2) ----
        {
            float* wg = wout + ((size_t)bh * S + q0 + wm * 16) * S + j0 + wn * 64;
            #pragma unroll
            for (int i = 0; i < 8; i++) {
                int r = i * 2 + (lane >> 4);
                int c4 = (lane & 15) * 4;
                float4 x = *reinterpret_cast<const float4*>(Wc + r * PADW + c4);
                *reinterpret_cast<float4*>(wg + (size_t)r * S + c4) = x;
            }
        }

        // ---- C-frag -> A-frag via shuffles (validated) ----
        {
            const int srcA = (lane & 28) | (tx >> 1);
            const int srcB = srcA + 2;
            #pragma unroll
            for (int g = 0; g < 8; g++) {
                float c0 = cacc[g][0], c1 = cacc[g][1];
                float c2 = cacc[g][2], c3 = cacc[g][3];
                float t0 = __shfl_sync(0xffffffffu, c0, srcA);
                float t1 = __shfl_sync(0xffffffffu, c1, srcA);
                float u0 = __shfl_sync(0xffffffffu, c0, srcB);
                float u1 = __shfl_sync(0xffffffffu, c1, srcB);
                float a0 = (tx & 1) ? t1 : t0;
                float a2 = (tx & 1) ? u1 : u0;
                t0 = __shfl_sync(0xffffffffu, c2, srcA);
                t1 = __shfl_sync(0xffffffffu, c3, srcA);
                u0 = __shfl_sync(0xffffffffu, c2, srcB);
                u1 = __shfl_sync(0xffffffffu, c3, srcB);
                float a1 = (tx & 1) ? t1 : t0;
                float a3 = (tx & 1) ? u1 : u0;
                cacc[g][0] = a0; cacc[g][1] = a1;
                cacc[g][2] = a2; cacc[g][3] = a3;
            }
        }

        // ---- PV: pacc += e(own 64-j slice) @ V(slice, all 64 d) ----
        #pragma unroll
        for (int g = 0; g < 8; g++) {
            #pragma unroll
            for (int ndt = 0; ndt < 8; ndt++) {
                const float* vb = Vs + (wn * 64 + g * 8 + tx) * PADV + ndt * 8 + ty;
                uint32_t b0 = f2u(vb[0]), b1 = f2u(vb[4 * PADV]);
                mma8(pacc[ndt], f2u(cacc[g][0]), f2u(cacc[g][1]),
                     f2u(cacc[g][2]), f2u(cacc[g][3]), b0, b1);
            }
        }
        __syncthreads();

        // ---- store prefetched tile to smem ----
        if (jt < 15) {
            #pragma unroll
            for (int i = 0; i < 4; i++) {
                int idx = i * NT + tid;
                int r = idx >> 4, c4 = (idx & 15) * 4;
                *reinterpret_cast<float4*>(Ks + r * PADK + c4) = rna4(kpre[i]);
                *reinterpret_cast<float4*>(Vs + r * PADV + c4) = rna4(vpre[i]);
            }
            __syncthreads();
        }
    }

    // ---- row sums -> sinv ----
    #pragma unroll
    for (int i = 0; i < 2; i++) {
        er2[i] += __shfl_xor_sync(0xffffffffu, er2[i], 1);
        er2[i] += __shfl_xor_sync(0xffffffffu, er2[i], 2);
    }
    if (tx == 0) {
        Sr[wn * 128 + wm * 16 + ty]     = er2[0];
        Sr[wn * 128 + wm * 16 + ty + 8] = er2[1];
    }
    __syncthreads();
    if (tid < 128) Sr[512 + tid] = 1.0f / (Sr[tid] + Sr[128 + tid]);
    __syncthreads();
    const float* sinv = Sr + 512;

    // ---- cross-wn reduction of pacc through smem (Q/K region dead) ----
    #pragma unroll
    for (int ndt = 0; ndt < 8; ndt++) {
        float* rp = red + ((wn * 128 + wm * 16 + ty) * PADR + ndt * 8 + 2 * tx);
        rp[0] = pacc[ndt][0]; rp[1] = pacc[ndt][1];
        rp[8 * PADR] = pacc[ndt][2]; rp[8 * PADR + 1] = pacc[ndt][3];
    }
    __syncthreads();
    #pragma unroll
    for (int i = 0; i < 4; i++) {
        int idx = i * NT + tid;
        int row = idx >> 4, c4 = (idx & 15) * 4;
        float4 s = *reinterpret_cast<const float4*>(red + (size_t)row * PADR + c4);
        float4 t = *reinterpret_cast<const float4*>(red + (size_t)(128 + row) * PADR + c4);
        const float iv = sinv[row];
        s.x = (s.x + t.x) * iv; s.y = (s.y + t.y) * iv;
        s.z = (s.z + t.z) * iv; s.w = (s.w + t.w) * iv;
        *reinterpret_cast<float4*>(out + ((size_t)bh * S + q0 + row) * D + c4) = s;
    }

    // ---- normalize this CTA's W block in place (reads hit L2; writes stream out) ----
    {
        float* wg = wout + ((size_t)bh * S + q0) * S;
        #pragma unroll 4
        for (int i = 0; i < 128; i++) {
            int idx = i * NT + tid;
            int r = idx >> 9, c4 = (idx & 511) * 4;
            float4* p = reinterpret_cast<float4*>(wg + (size_t)r * S + c4);
            float4 x = *p;
            const float iv = sinv[r];
            x.x *= iv; x.y *= iv; x.z *= iv; x.w *= iv;
            __stcs(p, x);
        }
    }
}

extern "C" void kernel_launch(void* const* d_in, const int* in_sizes, int n_in,
                              void* d_out, int out_size)
{
    const float* q = (const float*)d_in[0];
    const float* k = (const float*)d_in[1];
    const float* v = (const float*)d_in[2];
    const uint32_t* mask = (const uint32_t*)d_in[3];

    float* out  = (float*)d_out;
    float* wout = out + (size_t)B * H * S * D;

    static bool configured = false;
    if (!configured) {
        cudaFuncSetAttribute(sdpa_mma, cudaFuncAttributeMaxDynamicSharedMemorySize, SMEM_TOT);
        configured = true;
    }
    maskbit<<<B * S, 256>>>(mask);
    sdpa_mma<<<B * H * 16, NT, SMEM_TOT>>>(q, k, v, out, wout);
}

// round 15
// speedup vs baseline: 1.1411x; 1.1411x over previous
#include <cuda_runtime.h>
#include <cstdint>

constexpr int B = 2, H = 16, S = 2048, D = 64;
constexpr int NT = 512;                       // 16 warps: 8(m) x 2(n)
constexpr float SCALE = 0.125f * 1.4426950408889634f;  // (1/sqrt(64))*log2(e)

__device__ __align__(8) uint32_t g_mb[(size_t)B * S * 64];   // bit mask: 64 u32 words/row

// ---- smem map (bytes) ----
constexpr int PADK = 68;   // Q/K row pad: ldmatrix conflict-free
constexpr int PADV = 72;   // V row pad: scalar B-frags conflict-free
constexpr int PADW = 68;   // per-warp W chunk rows
constexpr int PADR = 68;
constexpr int SM_Q  = 0;                      // [128][68]
constexpr int SM_K0 = 34816;                  // [128][68] buffer 0
constexpr int SM_K1 = 69632;                  // [128][68] buffer 1
constexpr int SM_V  = 104448;                 // [128][72]
constexpr int SM_W  = 141312;                 // 16 warps x [16][68]
constexpr int SM_SR = 210944;                 // 640 floats
constexpr int SMEM_TOT = 213504;

__device__ __forceinline__ float tf32_rna(float x) {
    uint32_t b; asm("cvt.rna.tf32.f32 %0, %1;" : "=r"(b) : "f"(x));
    return __uint_as_float(b);
}
__device__ __forceinline__ float ex2f(float x) {
    float y; asm("ex2.approx.ftz.f32 %0, %1;" : "=f"(y) : "f"(x)); return y;
}
__device__ __forceinline__ void mma8(float* c, uint32_t a0, uint32_t a1, uint32_t a2, uint32_t a3,
                                     uint32_t b0, uint32_t b1) {
    asm volatile("mma.sync.aligned.m16n8k8.row.col.f32.tf32.tf32.f32 "
                 "{%0,%1,%2,%3},{%4,%5,%6,%7},{%8,%9},{%0,%1,%2,%3};"
                 : "+f"(c[0]), "+f"(c[1]), "+f"(c[2]), "+f"(c[3])
                 : "r"(a0), "r"(a1), "r"(a2), "r"(a3), "r"(b0), "r"(b1));
}
#define LDSM4(r, a)                                                             \
    asm volatile("ldmatrix.sync.aligned.m8n8.x4.shared.b16 {%0,%1,%2,%3},[%4];" \
                 : "=r"((r)[0]), "=r"((r)[1]), "=r"((r)[2]), "=r"((r)[3]) : "r"(a))

__device__ __forceinline__ uint32_t f2u(float x) { return __float_as_uint(x); }
__device__ __forceinline__ float4 rna4(float4 x) {
    x.x = tf32_rna(x.x); x.y = tf32_rna(x.y);
    x.z = tf32_rna(x.z); x.w = tf32_rna(x.w);
    return x;
}

// ---------------- pre-kernel: mask -> bits (handles int32 or byte bool) ----------------
__global__ __launch_bounds__(256) void maskbit(const uint32_t* __restrict__ m) {
    __shared__ int swide;
    const int t = threadIdx.x, lane = t & 31, w = t >> 5;
    const size_t row = blockIdx.x;
    if (t == 0) {
        int wide = 1;
        for (int i = 0; i < 256; i++) {
            uint32_t x = m[i];
            if (x > 1u) { wide = (x == 0x3F800000u) ? 1 : 0; break; }
        }
        swide = wide;
    }
    __syncthreads();
    uint32_t* dst = g_mb + row * 64;
    if (swide) {
        const uint32_t* src = m + row * S;
        #pragma unroll
        for (int it = 0; it < 8; it++) {
            int j = (w * 8 + it) * 32 + lane;
            uint32_t bal = __ballot_sync(0xffffffffu, src[j] != 0u);
            if (lane == 0) dst[w * 8 + it] = bal;
        }
    } else {
        const unsigned char* src = reinterpret_cast<const unsigned char*>(m) + row * S;
        #pragma unroll
        for (int it = 0; it < 8; it++) {
            int j = (w * 8 + it) * 32 + lane;
            uint32_t bal = __ballot_sync(0xffffffffu, src[j] != 0);
            if (lane == 0) dst[w * 8 + it] = bal;
        }
    }
}

// ---------------- main kernel ----------------
__global__ __launch_bounds__(NT, 1)
void sdpa_mma(const float* __restrict__ q, const float* __restrict__ k,
              const float* __restrict__ v,
              float* __restrict__ out, float* __restrict__ wout)
{
    extern __shared__ char sm[];
    float* Qs = reinterpret_cast<float*>(sm + SM_Q);
    float* Vs = reinterpret_cast<float*>(sm + SM_V);
    float* Sr = reinterpret_cast<float*>(sm + SM_SR);
    float* red = reinterpret_cast<float*>(sm);        // epilogue reuse of Q region

    const uint32_t SB = (uint32_t)__cvta_generic_to_shared(sm);
    const uint32_t SQ = SB + SM_Q, SK0 = SB + SM_K0;
    constexpr uint32_t KBUF = SM_K1 - SM_K0;           // 34816

    const int tid = threadIdx.x, lane = tid & 31, wid = tid >> 5;
    const int wm = wid >> 1, wn = wid & 1;             // 8(m) x 2(n)
    const int ty = lane >> 2, tx = lane & 3;

    const int bx = blockIdx.x, bh = bx >> 4, q0 = (bx & 15) * 128, b = bh >> 4;

    // per-warp private W chunk [16][PADW]
    float* Wc = reinterpret_cast<float*>(sm + SM_W) + wid * 16 * PADW;

    // ldmatrix bases
    const int lr = lane & 15;
    const int csel = (lane >> 4) * 4;
    const uint32_t qfb = SQ + (uint32_t)(((wm * 16 + lr) * PADK + csel) * 4);
    uint32_t kfb[4];
    #pragma unroll
    for (int p = 0; p < 4; p++) {
        const int krow = wn * 64 + p * 16 + ((lane >> 4) & 1) * 8 + (lane & 7);
        kfb[p] = SK0 + (uint32_t)((krow * PADK + ((lane >> 3) & 1) * 4) * 4);
    }

    // staging (r, c4) for this thread
    float* Kst0 = reinterpret_cast<float*>(sm + SM_K0);
    float* Kst1 = reinterpret_cast<float*>(sm + SM_K1);

    // ---- stage Q once (scaled, rna) ----
    {
        const float4* qg = reinterpret_cast<const float4*>(q + ((size_t)bh * S + q0) * D);
        #pragma unroll
        for (int i = 0; i < 4; i++) {
            int idx = i * NT + tid;
            int r = idx >> 4, c4 = (idx & 15) * 4;
            float4 x = qg[idx];
            x.x = tf32_rna(x.x * SCALE); x.y = tf32_rna(x.y * SCALE);
            x.z = tf32_rna(x.z * SCALE); x.w = tf32_rna(x.w * SCALE);
            *reinterpret_cast<float4*>(Qs + r * PADK + c4) = x;
        }
    }

    // ---- stage K/V tile 0 (K -> buffer 0) ----
    const float4* kg0 = reinterpret_cast<const float4*>(k + (size_t)bh * S * D);
    const float4* vg0 = reinterpret_cast<const float4*>(v + (size_t)bh * S * D);
    {
        #pragma unroll
        for (int i = 0; i < 4; i++) {
            int idx = i * NT + tid;
            int r = idx >> 4, c4 = (idx & 15) * 4;
            *reinterpret_cast<float4*>(Kst0 + r * PADK + c4) = rna4(kg0[idx]);
            *reinterpret_cast<float4*>(Vs + r * PADV + c4) = rna4(vg0[idx]);
        }
    }
    __syncthreads();

    float pacc[8][4];
    #pragma unroll
    for (int n = 0; n < 8; n++)
        #pragma unroll
        for (int i = 0; i < 4; i++) pacc[n][i] = 0.f;
    float er2[2] = {0.f, 0.f};

    // bit-mask row pointers (rows r0 = q0+wm*16+ty, r1 = +8)
    const uint32_t* mb0 = g_mb + ((size_t)(b * S + q0 + wm * 16 + ty)) * 64 + wn * 2;
    const uint32_t* mb1 = mb0 + 8 * 64;

    float4 kpre[4], vpre[4];

    for (int jt = 0; jt < 16; jt++) {
        const int j0 = jt * 128;
        const uint32_t kboff = (uint32_t)((jt & 1) * KBUF);

        // ---- prefetch next K/V tile + this tile's mask bits (hidden under QK) ----
        if (jt < 15) {
            const float4* kg = kg0 + (size_t)(j0 + 128) * (D / 4);
            const float4* vg = vg0 + (size_t)(j0 + 128) * (D / 4);
            #pragma unroll
            for (int i = 0; i < 4; i++) {
                kpre[i] = kg[i * NT + tid];
                vpre[i] = vg[i * NT + tid];
            }
        }
        const uint64_t w0 = *reinterpret_cast<const uint64_t*>(mb0 + jt * 4);
        const uint64_t w1 = *reinterpret_cast<const uint64_t*>(mb1 + jt * 4);

        // ---- QK^T: 16x64 block per warp (reads K buffer jt&1) ----
        float cacc[8][4];
        #pragma unroll
        for (int n = 0; n < 8; n++)
            #pragma unroll
            for (int i = 0; i < 4; i++) cacc[n][i] = 0.f;

        #pragma unroll
        for (int ks = 0; ks < 8; ks++) {
            uint32_t aa[4];
            LDSM4(aa, qfb + ks * 32);
            #pragma unroll
            for (int p = 0; p < 4; p++) {
                uint32_t bb[4];
                LDSM4(bb, kfb[p] + kboff + ks * 32);
                mma8(cacc[2 * p],     aa[0], aa[1], aa[2], aa[3], bb[0], bb[1]);
                mma8(cacc[2 * p + 1], aa[0], aa[1], aa[2], aa[3], bb[2], bb[3]);
            }
        }

        // ---- store prefetched K -> ALTERNATE buffer (no hazard: its last
        //      readers finished before the previous tile's end barrier) ----
        if (jt < 15) {
            float* kdst = (jt & 1) ? Kst0 : Kst1;   // buffer (jt+1)&1
            #pragma unroll
            for (int i = 0; i < 4; i++) {
                int idx = i * NT + tid;
                int r = idx >> 4, c4 = (idx & 15) * 4;
                *reinterpret_cast<float4*>(kdst + r * PADK + c4) = rna4(kpre[i]);
            }
        }

        // ---- mask(bits) + exp (rna) -> Wc + cacc, accumulate row sums ----
        {
            #pragma unroll
            for (int nt = 0; nt < 8; nt++) {
                const int sh = nt * 8 + tx * 2;
                float e00 = ((w0 >> sh) & 1ull) ? 1.0f : ex2f(cacc[nt][0]);
                float e01 = ((w0 >> (sh + 1)) & 1ull) ? 1.0f : ex2f(cacc[nt][1]);
                float e10 = ((w1 >> sh) & 1ull) ? 1.0f : ex2f(cacc[nt][2]);
                float e11 = ((w1 >> (sh + 1)) & 1ull) ? 1.0f : ex2f(cacc[nt][3]);
                e00 = tf32_rna(e00); e01 = tf32_rna(e01);
                e10 = tf32_rna(e10); e11 = tf32_rna(e11);
                er2[0] += e00 + e01;
                er2[1] += e10 + e11;
                cacc[nt][0] = e00; cacc[nt][1] = e01;
                cacc[nt][2] = e10; cacc[nt][3] = e11;
                *reinterpret_cast<float2*>(Wc + ty * PADW + nt * 8 + tx * 2)       = make_float2(e00, e01);
                *reinterpret_cast<float2*>(Wc + (ty + 8) * PADW + nt * 8 + tx * 2) = make_float2(e10, e11);
            }
        }

        // ---- warp-local W chunk -> gmem (coalesced, streaming) ----
        {
            float* wg = wout + ((size_t)bh * S + q0 + wm * 16) * S + j0 + wn * 64;
            #pragma unroll
            for (int i = 0; i < 8; i++) {
                int r = i * 2 + (lane >> 4);
                int c4 = (lane & 15) * 4;
                float4 x = *reinterpret_cast<const float4*>(Wc + r * PADW + c4);
                __stcs(reinterpret_cast<float4*>(wg + (size_t)r * S + c4), x);
            }
        }

        // ---- C-frag -> A-frag via shuffles (validated) ----
        {
            const int srcA = (lane & 28) | (tx >> 1);
            const int srcB = srcA + 2;
            #pragma unroll
            for (int g = 0; g < 8; g++) {
                float c0 = cacc[g][0], c1 = cacc[g][1];
                float c2 = cacc[g][2], c3 = cacc[g][3];
                float t0 = __shfl_sync(0xffffffffu, c0, srcA);
                float t1 = __shfl_sync(0xffffffffu, c1, srcA);
                float u0 = __shfl_sync(0xffffffffu, c0, srcB);
                float u1 = __shfl_sync(0xffffffffu, c1, srcB);
                float a0 = (tx & 1) ? t1 : t0;
                float a2 = (tx & 1) ? u1 : u0;
                t0 = __shfl_sync(0xffffffffu, c2, srcA);
                t1 = __shfl_sync(0xffffffffu, c3, srcA);
                u0 = __shfl_sync(0xffffffffu, c2, srcB);
                u1 = __shfl_sync(0xffffffffu, c3, srcB);
                float a1 = (tx & 1) ? t1 : t0;
                float a3 = (tx & 1) ? u1 : u0;
                cacc[g][0] = a0; cacc[g][1] = a1;
                cacc[g][2] = a2; cacc[g][3] = a3;
            }
        }

        // ---- PV: pacc += e(own 64-j slice) @ V(slice, all 64 d) ----
        #pragma unroll
        for (int g = 0; g < 8; g++) {
            #pragma unroll
            for (int ndt = 0; ndt < 8; ndt++) {
                const float* vb = Vs + (wn * 64 + g * 8 + tx) * PADV + ndt * 8 + ty;
                uint32_t b0 = f2u(vb[0]), b1 = f2u(vb[4 * PADV]);
                mma8(pacc[ndt], f2u(cacc[g][0]), f2u(cacc[g][1]),
                     f2u(cacc[g][2]), f2u(cacc[g][3]), b0, b1);
            }
        }
        __syncthreads();

        // ---- store prefetched V (short critical section) ----
        if (jt < 15) {
            #pragma unroll
            for (int i = 0; i < 4; i++) {
                int idx = i * NT + tid;
                int r = idx >> 4, c4 = (idx & 15) * 4;
                *reinterpret_cast<float4*>(Vs + r * PADV + c4) = rna4(vpre[i]);
            }
            __syncthreads();
        }
    }

    // ---- row sums -> sinv ----
    #pragma unroll
    for (int i = 0; i < 2; i++) {
        er2[i] += __shfl_xor_sync(0xffffffffu, er2[i], 1);
        er2[i] += __shfl_xor_sync(0xffffffffu, er2[i], 2);
    }
    if (tx == 0) {
        Sr[wn * 128 + wm * 16 + ty]     = er2[0];
        Sr[wn * 128 + wm * 16 + ty + 8] = er2[1];
    }
    __syncthreads();
    if (tid < 128) Sr[512 + tid] = 1.0f / (Sr[tid] + Sr[128 + tid]);
    __syncthreads();
    const float* sinv = Sr + 512;

    // ---- cross-wn reduction of pacc through smem (Q region dead) ----
    #pragma unroll
    for (int ndt = 0; ndt < 8; ndt++) {
        float* rp = red + ((wn * 128 + wm * 16 + ty) * PADR + ndt * 8 + 2 * tx);
        rp[0] = pacc[ndt][0]; rp[1] = pacc[ndt][1];
        rp[8 * PADR] = pacc[ndt][2]; rp[8 * PADR + 1] = pacc[ndt][3];
    }
    __syncthreads();
    #pragma unroll
    for (int i = 0; i < 4; i++) {
        int idx = i * NT + tid;
        int row = idx >> 4, c4 = (idx & 15) * 4;
        float4 s = *reinterpret_cast<const float4*>(red + (size_t)row * PADR + c4);
        float4 t = *reinterpret_cast<const float4*>(red + (size_t)(128 + row) * PADR + c4);
        const float iv = sinv[row];
        s.x = (s.x + t.x) * iv; s.y = (s.y + t.y) * iv;
        s.z = (s.z + t.z) * iv; s.w = (s.w + t.w) * iv;
        *reinterpret_cast<float4*>(out + ((size_t)bh * S + q0 + row) * D + c4) = s;
    }

    // ---- normalize this CTA's W block in place (streaming, as R11) ----
    {
        float* wg = wout + ((size_t)bh * S + q0) * S;
        #pragma unroll 4
        for (int i = 0; i < 128; i++) {
            int idx = i * NT + tid;
            int r = idx >> 9, c4 = (idx & 511) * 4;
            float4* p = reinterpret_cast<float4*>(wg + (size_t)r * S + c4);
            float4 x = __ldcs(p);
            const float iv = sinv[r];
            x.x *= iv; x.y *= iv; x.z *= iv; x.w *= iv;
            __stcs(p, x);
        }
    }
}

extern "C" void kernel_launch(void* const* d_in, const int* in_sizes, int n_in,
                              void* d_out, int out_size)
{
    const float* q = (const float*)d_in[0];
    const float* k = (const float*)d_in[1];
    const float* v = (const float*)d_in[2];
    const uint32_t* mask = (const uint32_t*)d_in[3];

    float* out  = (float*)d_out;
    float* wout = out + (size_t)B * H * S * D;

    static bool configured = false;
    if (!configured) {
        cudaFuncSetAttribute(sdpa_mma, cudaFuncAttributeMaxDynamicSharedMemorySize, SMEM_TOT);
        configured = true;
    }
    maskbit<<<B * S, 256>>>(mask);
    sdpa_mma<<<B * H * 16, NT, SMEM_TOT>>>(q, k, v, out, wout);
}

// round 16
// speedup vs baseline: 1.1915x; 1.0442x over previous
#include <cuda_runtime.h>
#include <cstdint>

constexpr int B = 2, H = 16, S = 2048, D = 64;
constexpr int NT = 512;                       // 16 warps: 8(m) x 2(n)
constexpr float SCALE = 0.125f * 1.4426950408889634f;  // (1/sqrt(64))*log2(e)

__device__ __align__(8) uint32_t g_mb[(size_t)B * S * 64];   // bit mask: 64 u32 words/row

// ---- smem map (bytes) ----
constexpr int PADK = 68;   // Q/K row pad: ldmatrix conflict-free
constexpr int PADV = 72;   // V row pad: scalar B-frags conflict-free
constexpr int PADR = 68;
constexpr int SM_Q  = 0;                      // [128][68]
constexpr int SM_K0 = 34816;                  // [128][68] K buffer 0
constexpr int SM_K1 = 69632;                  // [128][68] K buffer 1
constexpr int SM_V0 = 104448;                 // [128][72] V buffer 0
constexpr int SM_V1 = 141312;                 // [128][72] V buffer 1
constexpr int SM_SR = 178176;                 // 640 floats
constexpr int SMEM_TOT = 180736;

__device__ __forceinline__ float tf32_rna(float x) {
    uint32_t b; asm("cvt.rna.tf32.f32 %0, %1;" : "=r"(b) : "f"(x));
    return __uint_as_float(b);
}
__device__ __forceinline__ float ex2f(float x) {
    float y; asm("ex2.approx.ftz.f32 %0, %1;" : "=f"(y) : "f"(x)); return y;
}
__device__ __forceinline__ void mma8(float* c, uint32_t a0, uint32_t a1, uint32_t a2, uint32_t a3,
                                     uint32_t b0, uint32_t b1) {
    asm volatile("mma.sync.aligned.m16n8k8.row.col.f32.tf32.tf32.f32 "
                 "{%0,%1,%2,%3},{%4,%5,%6,%7},{%8,%9},{%0,%1,%2,%3};"
                 : "+f"(c[0]), "+f"(c[1]), "+f"(c[2]), "+f"(c[3])
                 : "r"(a0), "r"(a1), "r"(a2), "r"(a3), "r"(b0), "r"(b1));
}
#define LDSM4(r, a)                                                             \
    asm volatile("ldmatrix.sync.aligned.m8n8.x4.shared.b16 {%0,%1,%2,%3},[%4];" \
                 : "=r"((r)[0]), "=r"((r)[1]), "=r"((r)[2]), "=r"((r)[3]) : "r"(a))

__device__ __forceinline__ uint32_t f2u(float x) { return __float_as_uint(x); }
__device__ __forceinline__ float4 rna4(float4 x) {
    x.x = tf32_rna(x.x); x.y = tf32_rna(x.y);
    x.z = tf32_rna(x.z); x.w = tf32_rna(x.w);
    return x;
}
__device__ __forceinline__ void st_cs2(float* p, float a, float b) {
    __stcs(reinterpret_cast<float2*>(p), make_float2(a, b));
}

// ---------------- pre-kernel: mask -> bits (handles int32 or byte bool) ----------------
__global__ __launch_bounds__(256) void maskbit(const uint32_t* __restrict__ m) {
    __shared__ int swide;
    const int t = threadIdx.x, lane = t & 31, w = t >> 5;
    const size_t row = blockIdx.x;
    if (t == 0) {
        int wide = 1;
        for (int i = 0; i < 256; i++) {
            uint32_t x = m[i];
            if (x > 1u) { wide = (x == 0x3F800000u) ? 1 : 0; break; }
        }
        swide = wide;
    }
    __syncthreads();
    uint32_t* dst = g_mb + row * 64;
    if (swide) {
        const uint32_t* src = m + row * S;
        #pragma unroll
        for (int it = 0; it < 8; it++) {
            int j = (w * 8 + it) * 32 + lane;
            uint32_t bal = __ballot_sync(0xffffffffu, src[j] != 0u);
            if (lane == 0) dst[w * 8 + it] = bal;
        }
    } else {
        const unsigned char* src = reinterpret_cast<const unsigned char*>(m) + row * S;
        #pragma unroll
        for (int it = 0; it < 8; it++) {
            int j = (w * 8 + it) * 32 + lane;
            uint32_t bal = __ballot_sync(0xffffffffu, src[j] != 0);
            if (lane == 0) dst[w * 8 + it] = bal;
        }
    }
}

// ---------------- main kernel ----------------
__global__ __launch_bounds__(NT, 1)
void sdpa_mma(const float* __restrict__ q, const float* __restrict__ k,
              const float* __restrict__ v,
              float* __restrict__ out, float* __restrict__ wout)
{
    extern __shared__ char sm[];
    float* Qs = reinterpret_cast<float*>(sm + SM_Q);
    float* Sr = reinterpret_cast<float*>(sm + SM_SR);
    float* red = reinterpret_cast<float*>(sm);        // epilogue reuse of Q region

    const uint32_t SB = (uint32_t)__cvta_generic_to_shared(sm);
    const uint32_t SQ = SB + SM_Q, SK0 = SB + SM_K0;
    constexpr uint32_t KBUF = SM_K1 - SM_K0;           // 34816
    constexpr int VBUFF = (SM_V1 - SM_V0) / 4;         // 9216 floats

    const int tid = threadIdx.x, lane = tid & 31, wid = tid >> 5;
    const int wm = wid >> 1, wn = wid & 1;             // 8(m) x 2(n)
    const int ty = lane >> 2, tx = lane & 3;

    const int bx = blockIdx.x, bh = bx >> 4, q0 = (bx & 15) * 128, b = bh >> 4;

    // ldmatrix bases
    const int lr = lane & 15;
    const int csel = (lane >> 4) * 4;
    const uint32_t qfb = SQ + (uint32_t)(((wm * 16 + lr) * PADK + csel) * 4);
    uint32_t kfb[4];
    #pragma unroll
    for (int p = 0; p < 4; p++) {
        const int krow = wn * 64 + p * 16 + ((lane >> 4) & 1) * 8 + (lane & 7);
        kfb[p] = SK0 + (uint32_t)((krow * PADK + ((lane >> 3) & 1) * 4) * 4);
    }

    float* Kst0 = reinterpret_cast<float*>(sm + SM_K0);
    float* Kst1 = reinterpret_cast<float*>(sm + SM_K1);
    float* Vs0  = reinterpret_cast<float*>(sm + SM_V0);
    float* Vs1  = reinterpret_cast<float*>(sm + SM_V1);

    // ---- stage Q once (scaled, rna) ----
    {
        const float4* qg = reinterpret_cast<const float4*>(q + ((size_t)bh * S + q0) * D);
        #pragma unroll
        for (int i = 0; i < 4; i++) {
            int idx = i * NT + tid;
            int r = idx >> 4, c4 = (idx & 15) * 4;
            float4 x = qg[idx];
            x.x = tf32_rna(x.x * SCALE); x.y = tf32_rna(x.y * SCALE);
            x.z = tf32_rna(x.z * SCALE); x.w = tf32_rna(x.w * SCALE);
            *reinterpret_cast<float4*>(Qs + r * PADK + c4) = x;
        }
    }

    // ---- stage K/V tile 0 (buffers 0) ----
    const float4* kg0 = reinterpret_cast<const float4*>(k + (size_t)bh * S * D);
    const float4* vg0 = reinterpret_cast<const float4*>(v + (size_t)bh * S * D);
    {
        #pragma unroll
        for (int i = 0; i < 4; i++) {
            int idx = i * NT + tid;
            int r = idx >> 4, c4 = (idx & 15) * 4;
            *reinterpret_cast<float4*>(Kst0 + r * PADK + c4) = rna4(kg0[idx]);
            *reinterpret_cast<float4*>(Vs0 + r * PADV + c4) = rna4(vg0[idx]);
        }
    }
    __syncthreads();

    float pacc[8][4];
    #pragma unroll
    for (int n = 0; n < 8; n++)
        #pragma unroll
        for (int i = 0; i < 4; i++) pacc[n][i] = 0.f;
    float er2[2] = {0.f, 0.f};

    // bit-mask row pointers (rows r0 = q0+wm*16+ty, r1 = +8)
    const uint32_t* mb0 = g_mb + ((size_t)(b * S + q0 + wm * 16 + ty)) * 64 + wn * 2;
    const uint32_t* mb1 = mb0 + 8 * 64;

    // W gmem base rows for direct fragment stores
    float* wr0 = wout + ((size_t)bh * S + q0 + wm * 16 + ty) * S + wn * 64 + tx * 2;
    float* wr1 = wr0 + 8 * S;

    float4 kpre[4], vpre[4];

    for (int jt = 0; jt < 16; jt++) {
        const int j0 = jt * 128;
        const uint32_t kboff = (uint32_t)((jt & 1) * KBUF);
        const float* Vcur = (jt & 1) ? Vs1 : Vs0;

        // ---- prefetch next K/V tile + this tile's mask bits (hidden under QK) ----
        if (jt < 15) {
            const float4* kg = kg0 + (size_t)(j0 + 128) * (D / 4);
            const float4* vg = vg0 + (size_t)(j0 + 128) * (D / 4);
            #pragma unroll
            for (int i = 0; i < 4; i++) {
                kpre[i] = kg[i * NT + tid];
                vpre[i] = vg[i * NT + tid];
            }
        }
        const uint64_t w0 = *reinterpret_cast<const uint64_t*>(mb0 + jt * 4);
        const uint64_t w1 = *reinterpret_cast<const uint64_t*>(mb1 + jt * 4);

        // ---- QK^T: 16x64 block per warp (reads K buffer jt&1) ----
        float cacc[8][4];
        #pragma unroll
        for (int n = 0; n < 8; n++)
            #pragma unroll
            for (int i = 0; i < 4; i++) cacc[n][i] = 0.f;

        #pragma unroll
        for (int ks = 0; ks < 8; ks++) {
            uint32_t aa[4];
            LDSM4(aa, qfb + ks * 32);
            #pragma unroll
            for (int p = 0; p < 4; p++) {
                uint32_t bb[4];
                LDSM4(bb, kfb[p] + kboff + ks * 32);
                mma8(cacc[2 * p],     aa[0], aa[1], aa[2], aa[3], bb[0], bb[1]);
                mma8(cacc[2 * p + 1], aa[0], aa[1], aa[2], aa[3], bb[2], bb[3]);
            }
        }

        // ---- store prefetched K -> ALTERNATE buffer (no hazard) ----
        if (jt < 15) {
            float* kdst = (jt & 1) ? Kst0 : Kst1;
            #pragma unroll
            for (int i = 0; i < 4; i++) {
                int idx = i * NT + tid;
                int r = idx >> 4, c4 = (idx & 15) * 4;
                *reinterpret_cast<float4*>(kdst + r * PADK + c4) = rna4(kpre[i]);
            }
        }

        // ---- mask(bits) + exp (rna), row sums, direct __stcs W fragment stores ----
        {
            float* wg0 = wr0 + j0;
            float* wg1 = wr1 + j0;
            #pragma unroll
            for (int nt = 0; nt < 8; nt++) {
                const int sh = nt * 8 + tx * 2;
                float e00 = ((w0 >> sh) & 1ull) ? 1.0f : ex2f(cacc[nt][0]);
                float e01 = ((w0 >> (sh + 1)) & 1ull) ? 1.0f : ex2f(cacc[nt][1]);
                float e10 = ((w1 >> sh) & 1ull) ? 1.0f : ex2f(cacc[nt][2]);
                float e11 = ((w1 >> (sh + 1)) & 1ull) ? 1.0f : ex2f(cacc[nt][3]);
                e00 = tf32_rna(e00); e01 = tf32_rna(e01);
                e10 = tf32_rna(e10); e11 = tf32_rna(e11);
                er2[0] += e00 + e01;
                er2[1] += e10 + e11;
                cacc[nt][0] = e00; cacc[nt][1] = e01;
                cacc[nt][2] = e10; cacc[nt][3] = e11;
                st_cs2(wg0 + nt * 8, e00, e01);
                st_cs2(wg1 + nt * 8, e10, e11);
            }
        }

        // ---- C-frag -> A-frag via shuffles (validated) ----
        {
            const int srcA = (lane & 28) | (tx >> 1);
            const int srcB = srcA + 2;
            #pragma unroll
            for (int g = 0; g < 8; g++) {
                float c0 = cacc[g][0], c1 = cacc[g][1];
                float c2 = cacc[g][2], c3 = cacc[g][3];
                float t0 = __shfl_sync(0xffffffffu, c0, srcA);
                float t1 = __shfl_sync(0xffffffffu, c1, srcA);
                float u0 = __shfl_sync(0xffffffffu, c0, srcB);
                float u1 = __shfl_sync(0xffffffffu, c1, srcB);
                float a0 = (tx & 1) ? t1 : t0;
                float a2 = (tx & 1) ? u1 : u0;
                t0 = __shfl_sync(0xffffffffu, c2, srcA);
                t1 = __shfl_sync(0xffffffffu, c3, srcA);
                u0 = __shfl_sync(0xffffffffu, c2, srcB);
                u1 = __shfl_sync(0xffffffffu, c3, srcB);
                float a1 = (tx & 1) ? t1 : t0;
                float a3 = (tx & 1) ? u1 : u0;
                cacc[g][0] = a0; cacc[g][1] = a1;
                cacc[g][2] = a2; cacc[g][3] = a3;
            }
        }

        // ---- PV: pacc += e(own 64-j slice) @ V(slice, all 64 d) ----
        #pragma unroll
        for (int g = 0; g < 8; g++) {
            #pragma unroll
            for (int ndt = 0; ndt < 8; ndt++) {
                const float* vb = Vcur + (wn * 64 + g * 8 + tx) * PADV + ndt * 8 + ty;
                uint32_t b0 = f2u(vb[0]), b1 = f2u(vb[4 * PADV]);
                mma8(pacc[ndt], f2u(cacc[g][0]), f2u(cacc[g][1]),
                     f2u(cacc[g][2]), f2u(cacc[g][3]), b0, b1);
            }
        }

        // ---- store prefetched V -> ALTERNATE buffer (no hazard) ----
        if (jt < 15) {
            float* vdst = (jt & 1) ? Vs0 : Vs1;
            #pragma unroll
            for (int i = 0; i < 4; i++) {
                int idx = i * NT + tid;
                int r = idx >> 4, c4 = (idx & 15) * 4;
                *reinterpret_cast<float4*>(vdst + r * PADV + c4) = rna4(vpre[i]);
            }
        }
        __syncthreads();   // single barrier per tile: alternate K/V buffers ready
    }

    // ---- row sums -> sinv ----
    #pragma unroll
    for (int i = 0; i < 2; i++) {
        er2[i] += __shfl_xor_sync(0xffffffffu, er2[i], 1);
        er2[i] += __shfl_xor_sync(0xffffffffu, er2[i], 2);
    }
    if (tx == 0) {
        Sr[wn * 128 + wm * 16 + ty]     = er2[0];
        Sr[wn * 128 + wm * 16 + ty + 8] = er2[1];
    }
    __syncthreads();
    if (tid < 128) Sr[512 + tid] = 1.0f / (Sr[tid] + Sr[128 + tid]);
    __syncthreads();
    const float* sinv = Sr + 512;

    // ---- cross-wn reduction of pacc through smem (Q region dead) ----
    #pragma unroll
    for (int ndt = 0; ndt < 8; ndt++) {
        float* rp = red + ((wn * 128 + wm * 16 + ty) * PADR + ndt * 8 + 2 * tx);
        rp[0] = pacc[ndt][0]; rp[1] = pacc[ndt][1];
        rp[8 * PADR] = pacc[ndt][2]; rp[8 * PADR + 1] = pacc[ndt][3];
    }
    __syncthreads();
    #pragma unroll
    for (int i = 0; i < 4; i++) {
        int idx = i * NT + tid;
        int row = idx >> 4, c4 = (idx & 15) * 4;
        float4 s = *reinterpret_cast<const float4*>(red + (size_t)row * PADR + c4);
        float4 t = *reinterpret_cast<const float4*>(red + (size_t)(128 + row) * PADR + c4);
        const float iv = sinv[row];
        s.x = (s.x + t.x) * iv; s.y = (s.y + t.y) * iv;
        s.z = (s.z + t.z) * iv; s.w = (s.w + t.w) * iv;
        *reinterpret_cast<float4*>(out + ((size_t)bh * S + q0 + row) * D + c4) = s;
    }

    // ---- normalize this CTA's W block in place (streaming, as R11/R15) ----
    {
        float* wg = wout + ((size_t)bh * S + q0) * S;
        #pragma unroll 4
        for (int i = 0; i < 128; i++) {
            int idx = i * NT + tid;
            int r = idx >> 9, c4 = (idx & 511) * 4;
            float4* p = reinterpret_cast<float4*>(wg + (size_t)r * S + c4);
            float4 x = __ldcs(p);
            const float iv = sinv[r];
            x.x *= iv; x.y *= iv; x.z *= iv; x.w *= iv;
            __stcs(p, x);
        }
    }
}

extern "C" void kernel_launch(void* const* d_in, const int* in_sizes, int n_in,
                              void* d_out, int out_size)
{
    const float* q = (const float*)d_in[0];
    const float* k = (const float*)d_in[1];
    const float* v = (const float*)d_in[2];
    const uint32_t* mask = (const uint32_t*)d_in[3];

    float* out  = (float*)d_out;
    float* wout = out + (size_t)B * H * S * D;

    static bool configured = false;
    if (!configured) {
        cudaFuncSetAttribute(sdpa_mma, cudaFuncAttributeMaxDynamicSharedMemorySize, SMEM_TOT);
        configured = true;
    }
    maskbit<<<B * S, 256>>>(mask);
    sdpa_mma<<<B * H * 16, NT, SMEM_TOT>>>(q, k, v, out, wout);
}

// round 17
// speedup vs baseline: 1.1997x; 1.0068x over previous
#include <cuda_runtime.h>
#include <cstdint>

constexpr int B = 2, H = 16, S = 2048, D = 64;
constexpr int NT = 512;                       // 16 warps: 8(m) x 2(n)
constexpr float SCALE = 0.125f * 1.4426950408889634f;  // (1/sqrt(64))*log2(e)

__device__ __align__(8) uint32_t g_mb[(size_t)B * S * 64];       // bit mask
__device__ __align__(16) float g_kr[(size_t)B * H * S * D];      // rna(K)
__device__ __align__(16) float g_vr[(size_t)B * H * S * D];      // rna(V)

// ---- smem map (bytes) ----
constexpr int PADK = 68;   // Q/K row pad: ldmatrix conflict-free (272B = 16B-aligned)
constexpr int PADV = 72;   // V row pad: scalar B-frags conflict-free (288B = 16B-aligned)
constexpr int PADR = 68;
constexpr int SM_Q  = 0;                      // [128][68]
constexpr int SM_K0 = 34816;                  // [128][68] K buffer 0
constexpr int SM_K1 = 69632;                  // [128][68] K buffer 1
constexpr int SM_V0 = 104448;                 // [128][72] V buffer 0
constexpr int SM_V1 = 141312;                 // [128][72] V buffer 1
constexpr int SM_SR = 178176;                 // 640 floats
constexpr int SMEM_TOT = 180736;

__device__ __forceinline__ float tf32_rna(float x) {
    uint32_t b; asm("cvt.rna.tf32.f32 %0, %1;" : "=r"(b) : "f"(x));
    return __uint_as_float(b);
}
__device__ __forceinline__ float ex2f(float x) {
    float y; asm("ex2.approx.ftz.f32 %0, %1;" : "=f"(y) : "f"(x)); return y;
}
__device__ __forceinline__ void mma8(float* c, uint32_t a0, uint32_t a1, uint32_t a2, uint32_t a3,
                                     uint32_t b0, uint32_t b1) {
    asm volatile("mma.sync.aligned.m16n8k8.row.col.f32.tf32.tf32.f32 "
                 "{%0,%1,%2,%3},{%4,%5,%6,%7},{%8,%9},{%0,%1,%2,%3};"
                 : "+f"(c[0]), "+f"(c[1]), "+f"(c[2]), "+f"(c[3])
                 : "r"(a0), "r"(a1), "r"(a2), "r"(a3), "r"(b0), "r"(b1));
}
#define LDSM4(r, a)                                                             \
    asm volatile("ldmatrix.sync.aligned.m8n8.x4.shared.b16 {%0,%1,%2,%3},[%4];" \
                 : "=r"((r)[0]), "=r"((r)[1]), "=r"((r)[2]), "=r"((r)[3]) : "r"(a))
#define CPA16(d, s)   asm volatile("cp.async.ca.shared.global [%0],[%1],16;" :: "r"(d), "l"(s))
#define CPA_COMMIT()  asm volatile("cp.async.commit_group;" ::: "memory")
#define CPA_WAIT0()   asm volatile("cp.async.wait_group 0;" ::: "memory")

__device__ __forceinline__ uint32_t f2u(float x) { return __float_as_uint(x); }
__device__ __forceinline__ float4 rna4(float4 x) {
    x.x = tf32_rna(x.x); x.y = tf32_rna(x.y);
    x.z = tf32_rna(x.z); x.w = tf32_rna(x.w);
    return x;
}
__device__ __forceinline__ void st_cs2(float* p, float a, float b) {
    __stcs(reinterpret_cast<float2*>(p), make_float2(a, b));
}

// ---------------- pre-kernel: mask -> bits (handles int32 or byte bool) ----------------
__global__ __launch_bounds__(256) void maskbit(const uint32_t* __restrict__ m) {
    __shared__ int swide;
    const int t = threadIdx.x, lane = t & 31, w = t >> 5;
    const size_t row = blockIdx.x;
    if (t == 0) {
        int wide = 1;
        for (int i = 0; i < 256; i++) {
            uint32_t x = m[i];
            if (x > 1u) { wide = (x == 0x3F800000u) ? 1 : 0; break; }
        }
        swide = wide;
    }
    __syncthreads();
    uint32_t* dst = g_mb + row * 64;
    if (swide) {
        const uint32_t* src = m + row * S;
        #pragma unroll
        for (int it = 0; it < 8; it++) {
            int j = (w * 8 + it) * 32 + lane;
            uint32_t bal = __ballot_sync(0xffffffffu, src[j] != 0u);
            if (lane == 0) dst[w * 8 + it] = bal;
        }
    } else {
        const unsigned char* src = reinterpret_cast<const unsigned char*>(m) + row * S;
        #pragma unroll
        for (int it = 0; it < 8; it++) {
            int j = (w * 8 + it) * 32 + lane;
            uint32_t bal = __ballot_sync(0xffffffffu, src[j] != 0);
            if (lane == 0) dst[w * 8 + it] = bal;
        }
    }
}

// ---------------- pre-kernel: rna-round K and V ----------------
__global__ __launch_bounds__(256) void rnakv(const float* __restrict__ k,
                                             const float* __restrict__ v) {
    const int idx = blockIdx.x * 256 + threadIdx.x;   // float4 index
    reinterpret_cast<float4*>(g_kr)[idx] = rna4(reinterpret_cast<const float4*>(k)[idx]);
    reinterpret_cast<float4*>(g_vr)[idx] = rna4(reinterpret_cast<const float4*>(v)[idx]);
}

// ---------------- main kernel ----------------
__global__ __launch_bounds__(NT, 1)
void sdpa_mma(const float* __restrict__ q,
              float* __restrict__ out, float* __restrict__ wout)
{
    extern __shared__ char sm[];
    float* Qs = reinterpret_cast<float*>(sm + SM_Q);
    float* Sr = reinterpret_cast<float*>(sm + SM_SR);
    float* red = reinterpret_cast<float*>(sm);        // epilogue reuse of Q region

    const uint32_t SB = (uint32_t)__cvta_generic_to_shared(sm);
    const uint32_t SQ = SB + SM_Q, SK0 = SB + SM_K0, SV0 = SB + SM_V0;
    constexpr uint32_t KBUF = SM_K1 - SM_K0;
    constexpr uint32_t VBUF = SM_V1 - SM_V0;

    const int tid = threadIdx.x, lane = tid & 31, wid = tid >> 5;
    const int wm = wid >> 1, wn = wid & 1;             // 8(m) x 2(n)
    const int ty = lane >> 2, tx = lane & 3;

    const int bx = blockIdx.x, bh = bx >> 4, q0 = (bx & 15) * 128, b = bh >> 4;

    const float* kr = g_kr + (size_t)bh * S * D;
    const float* vr = g_vr + (size_t)bh * S * D;

    // staging (r, c4) for this thread: 4 x 16B per tile per tensor
    const int str = tid >> 4;                 // rows str, str+32, str+64, str+96
    const int stc = (tid & 15) * 4;
    const uint32_t kst = SK0 + (uint32_t)((str * PADK + stc) * 4);
    const uint32_t vst = SV0 + (uint32_t)((str * PADV + stc) * 4);

    // ldmatrix bases
    const int lr = lane & 15;
    const int csel = (lane >> 4) * 4;
    const uint32_t qfb = SQ + (uint32_t)(((wm * 16 + lr) * PADK + csel) * 4);
    uint32_t kfb[4];
    #pragma unroll
    for (int p = 0; p < 4; p++) {
        const int krow = wn * 64 + p * 16 + ((lane >> 4) & 1) * 8 + (lane & 7);
        kfb[p] = SK0 + (uint32_t)((krow * PADK + ((lane >> 3) & 1) * 4) * 4);
    }

    // ---- prologue: async-stage K0/V0, stage Q (scaled, rna) ----
    #pragma unroll
    for (int i = 0; i < 4; i++) {
        CPA16(kst + (uint32_t)(i * 32 * PADK * 4), kr + (size_t)(str + i * 32) * D + stc);
        CPA16(vst + (uint32_t)(i * 32 * PADV * 4), vr + (size_t)(str + i * 32) * D + stc);
    }
    CPA_COMMIT();
    {
        const float4* qg = reinterpret_cast<const float4*>(q + ((size_t)bh * S + q0) * D);
        #pragma unroll
        for (int i = 0; i < 4; i++) {
            int idx = i * NT + tid;
            int r = idx >> 4, c4 = (idx & 15) * 4;
            float4 x = qg[idx];
            x.x = tf32_rna(x.x * SCALE); x.y = tf32_rna(x.y * SCALE);
            x.z = tf32_rna(x.z * SCALE); x.w = tf32_rna(x.w * SCALE);
            *reinterpret_cast<float4*>(Qs + r * PADK + c4) = x;
        }
    }
    CPA_WAIT0();
    __syncthreads();

    // ---- persistent Q fragments (32 regs) ----
    uint32_t qf[8][4];
    #pragma unroll
    for (int ks = 0; ks < 8; ks++) LDSM4(qf[ks], qfb + ks * 32);

    float pacc[8][4];
    #pragma unroll
    for (int n = 0; n < 8; n++)
        #pragma unroll
        for (int i = 0; i < 4; i++) pacc[n][i] = 0.f;
    float er2[2] = {0.f, 0.f};

    const uint32_t* mb0 = g_mb + ((size_t)(b * S + q0 + wm * 16 + ty)) * 64 + wn * 2;
    const uint32_t* mb1 = mb0 + 8 * 64;

    float* wr0 = wout + ((size_t)bh * S + q0 + wm * 16 + ty) * S + wn * 64 + tx * 2;
    float* wr1 = wr0 + 8 * S;

    for (int jt = 0; jt < 16; jt++) {
        const int j0 = jt * 128;
        const uint32_t kboff = (uint32_t)((jt & 1) * KBUF);
        const uint32_t vboff = (uint32_t)((jt & 1) * VBUF);
        const float* Vcur = reinterpret_cast<const float*>(sm + SM_V0 + vboff);

        // ---- async-stage next K/V tile into alternate buffers ----
        if (jt < 15) {
            const float* kn = kr + (size_t)(j0 + 128) * D;
            const float* vn = vr + (size_t)(j0 + 128) * D;
            const uint32_t kd = kst + (KBUF - kboff);   // alternate K buffer
            const uint32_t vd = vst + (VBUF - vboff);   // alternate V buffer
            #pragma unroll
            for (int i = 0; i < 4; i++) {
                CPA16(kd + (uint32_t)(i * 32 * PADK * 4), kn + (size_t)(str + i * 32) * D + stc);
                CPA16(vd + (uint32_t)(i * 32 * PADV * 4), vn + (size_t)(str + i * 32) * D + stc);
            }
            CPA_COMMIT();
        }
        const uint64_t w0 = *reinterpret_cast<const uint64_t*>(mb0 + jt * 4);
        const uint64_t w1 = *reinterpret_cast<const uint64_t*>(mb1 + jt * 4);

        // ---- QK^T: 16x64 block per warp (persistent Q frags) ----
        float cacc[8][4];
        #pragma unroll
        for (int n = 0; n < 8; n++)
            #pragma unroll
            for (int i = 0; i < 4; i++) cacc[n][i] = 0.f;

        #pragma unroll
        for (int ks = 0; ks < 8; ks++) {
            #pragma unroll
            for (int p = 0; p < 4; p++) {
                uint32_t bb[4];
                LDSM4(bb, kfb[p] + kboff + ks * 32);
                mma8(cacc[2 * p],     qf[ks][0], qf[ks][1], qf[ks][2], qf[ks][3], bb[0], bb[1]);
                mma8(cacc[2 * p + 1], qf[ks][0], qf[ks][1], qf[ks][2], qf[ks][3], bb[2], bb[3]);
            }
        }

        // ---- mask(bits) + exp (rna), row sums, direct __stcs W fragment stores ----
        {
            float* wg0 = wr0 + j0;
            float* wg1 = wr1 + j0;
            #pragma unroll
            for (int nt = 0; nt < 8; nt++) {
                const int sh = nt * 8 + tx * 2;
                float e00 = ((w0 >> sh) & 1ull) ? 1.0f : ex2f(cacc[nt][0]);
                float e01 = ((w0 >> (sh + 1)) & 1ull) ? 1.0f : ex2f(cacc[nt][1]);
                float e10 = ((w1 >> sh) & 1ull) ? 1.0f : ex2f(cacc[nt][2]);
                float e11 = ((w1 >> (sh + 1)) & 1ull) ? 1.0f : ex2f(cacc[nt][3]);
                e00 = tf32_rna(e00); e01 = tf32_rna(e01);
                e10 = tf32_rna(e10); e11 = tf32_rna(e11);
                er2[0] += e00 + e01;
                er2[1] += e10 + e11;
                cacc[nt][0] = e00; cacc[nt][1] = e01;
                cacc[nt][2] = e10; cacc[nt][3] = e11;
                st_cs2(wg0 + nt * 8, e00, e01);
                st_cs2(wg1 + nt * 8, e10, e11);
            }
        }

        // ---- C-frag -> A-frag via shuffles (validated) ----
        {
            const int srcA = (lane & 28) | (tx >> 1);
            const int srcB = srcA + 2;
            #pragma unroll
            for (int g = 0; g < 8; g++) {
                float c0 = cacc[g][0], c1 = cacc[g][1];
                float c2 = cacc[g][2], c3 = cacc[g][3];
                float t0 = __shfl_sync(0xffffffffu, c0, srcA);
                float t1 = __shfl_sync(0xffffffffu, c1, srcA);
                float u0 = __shfl_sync(0xffffffffu, c0, srcB);
                float u1 = __shfl_sync(0xffffffffu, c1, srcB);
                float a0 = (tx & 1) ? t1 : t0;
                float a2 = (tx & 1) ? u1 : u0;
                t0 = __shfl_sync(0xffffffffu, c2, srcA);
                t1 = __shfl_sync(0xffffffffu, c3, srcA);
                u0 = __shfl_sync(0xffffffffu, c2, srcB);
                u1 = __shfl_sync(0xffffffffu, c3, srcB);
                float a1 = (tx & 1) ? t1 : t0;
                float a3 = (tx & 1) ? u1 : u0;
                cacc[g][0] = a0; cacc[g][1] = a1;
                cacc[g][2] = a2; cacc[g][3] = a3;
            }
        }

        // ---- PV: pacc += e(own 64-j slice) @ V(slice, all 64 d) ----
        #pragma unroll
        for (int g = 0; g < 8; g++) {
            #pragma unroll
            for (int ndt = 0; ndt < 8; ndt++) {
                const float* vb = Vcur + (wn * 64 + g * 8 + tx) * PADV + ndt * 8 + ty;
                uint32_t b0 = f2u(vb[0]), b1 = f2u(vb[4 * PADV]);
                mma8(pacc[ndt], f2u(cacc[g][0]), f2u(cacc[g][1]),
                     f2u(cacc[g][2]), f2u(cacc[g][3]), b0, b1);
            }
        }

        if (jt < 15) CPA_WAIT0();
        __syncthreads();   // single barrier per tile: alternate K/V buffers ready
    }

    // ---- row sums -> sinv ----
    #pragma unroll
    for (int i = 0; i < 2; i++) {
        er2[i] += __shfl_xor_sync(0xffffffffu, er2[i], 1);
        er2[i] += __shfl_xor_sync(0xffffffffu, er2[i], 2);
    }
    if (tx == 0) {
        Sr[wn * 128 + wm * 16 + ty]     = er2[0];
        Sr[wn * 128 + wm * 16 + ty + 8] = er2[1];
    }
    __syncthreads();
    if (tid < 128) Sr[512 + tid] = 1.0f / (Sr[tid] + Sr[128 + tid]);
    __syncthreads();
    const float* sinv = Sr + 512;

    // ---- cross-wn reduction of pacc through smem (Q region dead) ----
    #pragma unroll
    for (int ndt = 0; ndt < 8; ndt++) {
        float* rp = red + ((wn * 128 + wm * 16 + ty) * PADR + ndt * 8 + 2 * tx);
        rp[0] = pacc[ndt][0]; rp[1] = pacc[ndt][1];
        rp[8 * PADR] = pacc[ndt][2]; rp[8 * PADR + 1] = pacc[ndt][3];
    }
    __syncthreads();
    #pragma unroll
    for (int i = 0; i < 4; i++) {
        int idx = i * NT + tid;
        int row = idx >> 4, c4 = (idx & 15) * 4;
        float4 s = *reinterpret_cast<const float4*>(red + (size_t)row * PADR + c4);
        float4 t = *reinterpret_cast<const float4*>(red + (size_t)(128 + row) * PADR + c4);
        const float iv = sinv[row];
        s.x = (s.x + t.x) * iv; s.y = (s.y + t.y) * iv;
        s.z = (s.z + t.z) * iv; s.w = (s.w + t.w) * iv;
        *reinterpret_cast<float4*>(out + ((size_t)bh * S + q0 + row) * D + c4) = s;
    }

    // ---- normalize this CTA's W block in place (streaming) ----
    {
        float* wg = wout + ((size_t)bh * S + q0) * S;
        #pragma unroll 4
        for (int i = 0; i < 128; i++) {
            int idx = i * NT + tid;
            int r = idx >> 9, c4 = (idx & 511) * 4;
            float4* p = reinterpret_cast<float4*>(wg + (size_t)r * S + c4);
            float4 x = __ldcs(p);
            const float iv = sinv[r];
            x.x *= iv; x.y *= iv; x.z *= iv; x.w *= iv;
            __stcs(p, x);
        }
    }
}

extern "C" void kernel_launch(void* const* d_in, const int* in_sizes, int n_in,
                              void* d_out, int out_size)
{
    const float* q = (const float*)d_in[0];
    const float* k = (const float*)d_in[1];
    const float* v = (const float*)d_in[2];
    const uint32_t* mask = (const uint32_t*)d_in[3];

    float* out  = (float*)d_out;
    float* wout = out + (size_t)B * H * S * D;

    static bool configured = false;
    if (!configured) {
        cudaFuncSetAttribute(sdpa_mma, cudaFuncAttributeMaxDynamicSharedMemorySize, SMEM_TOT);
        configured = true;
    }
    maskbit<<<B * S, 256>>>(mask);
    rnakv<<<(B * H * S * D / 4) / 256, 256>>>(k, v);
    sdpa_mma<<<B * H * 16, NT, SMEM_TOT>>>(q, out, wout);
}